// round 7
// baseline (speedup 1.0000x reference)
#include <cuda_runtime.h>

// ---------------------------------------------------------------------------
// MultiHeadedAttention with attention-propagation, fp32 baseline.
//   B=2, S=2048, D=1024, H=16, DK=64
// Pipeline:
//   1) Q/K/V = X @ W + b                     (gemm_nn_bias x3)
//   2) S1[b,h,q,k] = mask ? (q.k)/8 : 0      (qk_mask_kernel)
//   3) S2 = S1 @ prop^T                      (prop_gemm_kernel, 549 GF dominant)
//   4) masked softmax rows of S2 (nan->0)    (softmax_kernel)
//   5) ctx[b,q,h,:] = S2 @ V                 (av_kernel)
//   6) out = ctx @ Wo + bo                   (gemm_nn_bias)
// ---------------------------------------------------------------------------

#define Bc  2
#define Sc  2048
#define Dc  1024
#define Hc  16
#define DKc 64
#define BSc 4096           // B*S
#define BHc 32             // B*H

// Scratch (device globals: the alloc-free workaround).
__device__ float g_q[BSc * Dc];
__device__ float g_k[BSc * Dc];
__device__ float g_v[BSc * Dc];
__device__ float g_ctx[BSc * Dc];
__device__ float g_s1[134217728];   // [B*H, S, S] = 32*2048*2048
__device__ float g_s2[134217728];

// ---------------------------------------------------------------------------
// Shared 8x8-per-thread inner product step. As/Bs are [TK][128] smem tiles
// stored K-major (As[kk][m], Bs[kk][n]).
// ---------------------------------------------------------------------------
template <int TK>
__device__ __forceinline__ void mm8x8(float (*As)[128], float (*Bs)[128],
                                      float (&acc)[8][8], int tx, int ty) {
#pragma unroll
  for (int kk = 0; kk < TK; kk++) {
    float4 a0 = *(const float4*)&As[kk][ty * 8];
    float4 a1 = *(const float4*)&As[kk][ty * 8 + 4];
    float4 b0 = *(const float4*)&Bs[kk][tx * 8];
    float4 b1 = *(const float4*)&Bs[kk][tx * 8 + 4];
    float av[8] = {a0.x, a0.y, a0.z, a0.w, a1.x, a1.y, a1.z, a1.w};
    float bv[8] = {b0.x, b0.y, b0.z, b0.w, b1.x, b1.y, b1.z, b1.w};
#pragma unroll
    for (int i = 0; i < 8; i++)
#pragma unroll
      for (int j = 0; j < 8; j++) acc[i][j] = fmaf(av[i], bv[j], acc[i][j]);
  }
}

// ---------------------------------------------------------------------------
// C[4096,1024] = A[4096,1024] @ W[1024,1024] + bias  (NN, row-major)
// 128x128 block tile, TK=8, 256 threads, 8x8 per thread.
// ---------------------------------------------------------------------------
__global__ __launch_bounds__(256, 2) void gemm_nn_bias(
    const float* __restrict__ A, const float* __restrict__ W,
    const float* __restrict__ bias, float* __restrict__ C) {
  const int N = 1024, K = 1024;
  __shared__ __align__(16) float As[8][128];
  __shared__ __align__(16) float Bs[8][128];
  const int bm = blockIdx.y * 128;
  const int bn = blockIdx.x * 128;
  const int tid = threadIdx.x;
  const int tx = tid & 15, ty = tid >> 4;
  const int ar = tid >> 1, ac = (tid & 1) * 4;     // A tile 128x8: 1 float4/thr
  const int wr = tid >> 5, wc = (tid & 31) * 4;    // W tile 8x128: 1 float4/thr
  float acc[8][8];
#pragma unroll
  for (int i = 0; i < 8; i++)
#pragma unroll
    for (int j = 0; j < 8; j++) acc[i][j] = 0.f;

  const float* Ap = A + (size_t)(bm + ar) * K + ac;
  const float* Wp = W + (size_t)wr * N + bn + wc;

  for (int k0 = 0; k0 < K; k0 += 8) {
    float4 av = *(const float4*)(Ap + k0);
    float4 wv = *(const float4*)(Wp + (size_t)k0 * N);
    __syncthreads();
    As[ac + 0][ar] = av.x;
    As[ac + 1][ar] = av.y;
    As[ac + 2][ar] = av.z;
    As[ac + 3][ar] = av.w;
    *(float4*)&Bs[wr][wc] = wv;
    __syncthreads();
    mm8x8<8>(As, Bs, acc, tx, ty);
  }

#pragma unroll
  for (int i = 0; i < 8; i++) {
    const int m = bm + ty * 8 + i;
#pragma unroll
    for (int j4 = 0; j4 < 2; j4++) {
      const int n = bn + tx * 8 + j4 * 4;
      float4 o;
      o.x = acc[i][j4 * 4 + 0] + bias[n + 0];
      o.y = acc[i][j4 * 4 + 1] + bias[n + 1];
      o.z = acc[i][j4 * 4 + 2] + bias[n + 2];
      o.w = acc[i][j4 * 4 + 3] + bias[n + 3];
      *(float4*)&C[(size_t)m * N + n] = o;
    }
  }
}

// ---------------------------------------------------------------------------
// S1[bh,q,n] = mask[b,0,q,n] ? (Q[b,q,h,:] . K[b,n,h,:]) / 8 : 0
// Per (b,h): NT GEMM M=N=2048, K=64. 128x128 tile, TK=16.
// ---------------------------------------------------------------------------
__global__ __launch_bounds__(256, 2) void qk_mask_kernel(const int* __restrict__ mask) {
  const int bh = blockIdx.z;
  const int b = bh >> 4, h = bh & 15;
  const int q0 = blockIdx.y * 128;
  const int n0 = blockIdx.x * 128;
  __shared__ __align__(16) float As[16][128];
  __shared__ __align__(16) float Bs[16][128];
  const int tid = threadIdx.x;
  const int tx = tid & 15, ty = tid >> 4;
  // 128 rows x 16 cols tile = 512 float4, 2 per thread (same row, cols c0/c0+4)
  const int idx = tid * 2;
  const int r = idx >> 2;          // 0..127
  const int c0 = (idx & 3) * 4;    // 0 or 8
  const int c1 = c0 + 4;

  const float* Qb = g_q + ((size_t)b * Sc + q0) * Dc + h * DKc;
  const float* Kb = g_k + ((size_t)b * Sc + n0) * Dc + h * DKc;

  float acc[8][8];
#pragma unroll
  for (int i = 0; i < 8; i++)
#pragma unroll
    for (int j = 0; j < 8; j++) acc[i][j] = 0.f;

  for (int kc = 0; kc < DKc; kc += 16) {
    float4 qa = *(const float4*)(Qb + (size_t)r * Dc + kc + c0);
    float4 qd = *(const float4*)(Qb + (size_t)r * Dc + kc + c1);
    float4 ka = *(const float4*)(Kb + (size_t)r * Dc + kc + c0);
    float4 kd = *(const float4*)(Kb + (size_t)r * Dc + kc + c1);
    __syncthreads();
    As[c0 + 0][r] = qa.x; As[c0 + 1][r] = qa.y; As[c0 + 2][r] = qa.z; As[c0 + 3][r] = qa.w;
    As[c1 + 0][r] = qd.x; As[c1 + 1][r] = qd.y; As[c1 + 2][r] = qd.z; As[c1 + 3][r] = qd.w;
    Bs[c0 + 0][r] = ka.x; Bs[c0 + 1][r] = ka.y; Bs[c0 + 2][r] = ka.z; Bs[c0 + 3][r] = ka.w;
    Bs[c1 + 0][r] = kd.x; Bs[c1 + 1][r] = kd.y; Bs[c1 + 2][r] = kd.z; Bs[c1 + 3][r] = kd.w;
    __syncthreads();
    mm8x8<16>(As, Bs, acc, tx, ty);
  }

#pragma unroll
  for (int i = 0; i < 8; i++) {
    const int m = q0 + ty * 8 + i;
    const size_t mrow = ((size_t)b * Sc + m) * Sc;
    const size_t orow = ((size_t)bh * Sc + m) * Sc;
#pragma unroll
    for (int j = 0; j < 8; j++) {
      const int n = n0 + tx * 8 + j;
      g_s1[orow + n] = mask[mrow + n] ? acc[i][j] * 0.125f : 0.f;
    }
  }
}

// ---------------------------------------------------------------------------
// S2[m,l] = sum_k S1[m,k] * P[l,k]   (NT; M=65536, N=2048, K=2048) -- 549 GF
// ---------------------------------------------------------------------------
__global__ __launch_bounds__(256, 2) void prop_gemm_kernel(const float* __restrict__ P) {
  __shared__ __align__(16) float As[8][128];
  __shared__ __align__(16) float Bs[8][128];
  const int bm = blockIdx.y * 128;
  const int bn = blockIdx.x * 128;
  const int tid = threadIdx.x;
  const int tx = tid & 15, ty = tid >> 4;
  const int r = tid >> 1, c = (tid & 1) * 4;  // 128x8 tiles: 1 float4/thr each

  const float* Ap = g_s1 + (size_t)(bm + r) * Sc + c;
  const float* Bp = P + (size_t)(bn + r) * Sc + c;

  float acc[8][8];
#pragma unroll
  for (int i = 0; i < 8; i++)
#pragma unroll
    for (int j = 0; j < 8; j++) acc[i][j] = 0.f;

  for (int k0 = 0; k0 < Sc; k0 += 8) {
    float4 av = *(const float4*)(Ap + k0);
    float4 bv = *(const float4*)(Bp + k0);
    __syncthreads();
    As[c + 0][r] = av.x; As[c + 1][r] = av.y; As[c + 2][r] = av.z; As[c + 3][r] = av.w;
    Bs[c + 0][r] = bv.x; Bs[c + 1][r] = bv.y; Bs[c + 2][r] = bv.z; Bs[c + 3][r] = bv.w;
    __syncthreads();
    mm8x8<8>(As, Bs, acc, tx, ty);
  }

#pragma unroll
  for (int i = 0; i < 8; i++) {
    const size_t orow = (size_t)(bm + ty * 8 + i) * Sc;
#pragma unroll
    for (int j4 = 0; j4 < 2; j4++) {
      const int n = bn + tx * 8 + j4 * 4;
      float4 o;
      o.x = acc[i][j4 * 4 + 0];
      o.y = acc[i][j4 * 4 + 1];
      o.z = acc[i][j4 * 4 + 2];
      o.w = acc[i][j4 * 4 + 3];
      *(float4*)&g_s2[orow + n] = o;
    }
  }
}

// ---------------------------------------------------------------------------
// Masked softmax over last dim of S2 (in place). Fully-masked rows -> 0.
// One block (256 threads) per row; 65536 rows.
// ---------------------------------------------------------------------------
__global__ __launch_bounds__(256) void softmax_kernel(const int* __restrict__ mask) {
  const int row = blockIdx.x;           // (b*H+h)*S + q
  const int b = row >> 15;              // / (H*S)
  const int q = row & (Sc - 1);
  float* p = g_s2 + (size_t)row * Sc;
  const int* mrow = mask + ((size_t)b * Sc + q) * Sc;
  const int tid = threadIdx.x;
  __shared__ float red[256];

  float mx = -3.402823466e38f;
  for (int i = tid; i < Sc; i += 256)
    if (mrow[i]) mx = fmaxf(mx, p[i]);
  red[tid] = mx;
  __syncthreads();
  for (int s = 128; s > 0; s >>= 1) {
    if (tid < s) red[tid] = fmaxf(red[tid], red[tid + s]);
    __syncthreads();
  }
  mx = red[0];
  __syncthreads();

  float sum = 0.f;
  for (int i = tid; i < Sc; i += 256) {
    float e = mrow[i] ? expf(p[i] - mx) : 0.f;
    p[i] = e;
    sum += e;
  }
  red[tid] = sum;
  __syncthreads();
  for (int s = 128; s > 0; s >>= 1) {
    if (tid < s) red[tid] += red[tid + s];
    __syncthreads();
  }
  const float inv = red[0] > 0.f ? 1.f / red[0] : 0.f;  // nan_to_num for all-masked
  for (int i = tid; i < Sc; i += 256) p[i] *= inv;
}

// ---------------------------------------------------------------------------
// ctx[b,q,h,:] = sum_l S2[bh,q,l] * V[b,l,h,:]   (per bh: M=2048,N=64,K=2048)
// 128x64 block tile, TK=16, 256 threads, 8x4 per thread.
// ---------------------------------------------------------------------------
__global__ __launch_bounds__(256, 2) void av_kernel() {
  const int bh = blockIdx.z;
  const int b = bh >> 4, h = bh & 15;
  const int q0 = blockIdx.y * 128;
  __shared__ __align__(16) float As[16][128];  // P^T chunk: As[l][q]
  __shared__ __align__(16) float Bs[16][64];   // V chunk:   Bs[l][dk]
  const int tid = threadIdx.x;
  const int tx = tid & 15, ty = tid >> 4;
  const int idx = tid * 2;
  const int r = idx >> 2;
  const int c0 = (idx & 3) * 4;
  const int c1 = c0 + 4;
  const int vr = tid >> 4, vc = (tid & 15) * 4;  // V tile 16x64: 1 float4/thr

  const float* Pb = g_s2 + ((size_t)bh * Sc + q0) * Sc;
  const float* Vb = g_v + (size_t)b * Sc * Dc + h * DKc;

  float acc[8][4];
#pragma unroll
  for (int i = 0; i < 8; i++)
#pragma unroll
    for (int j = 0; j < 4; j++) acc[i][j] = 0.f;

  for (int l0 = 0; l0 < Sc; l0 += 16) {
    float4 pa = *(const float4*)(Pb + (size_t)r * Sc + l0 + c0);
    float4 pd = *(const float4*)(Pb + (size_t)r * Sc + l0 + c1);
    float4 vv = *(const float4*)(Vb + (size_t)(l0 + vr) * Dc + vc);
    __syncthreads();
    As[c0 + 0][r] = pa.x; As[c0 + 1][r] = pa.y; As[c0 + 2][r] = pa.z; As[c0 + 3][r] = pa.w;
    As[c1 + 0][r] = pd.x; As[c1 + 1][r] = pd.y; As[c1 + 2][r] = pd.z; As[c1 + 3][r] = pd.w;
    *(float4*)&Bs[vr][vc] = vv;
    __syncthreads();
#pragma unroll
    for (int kk = 0; kk < 16; kk++) {
      float4 a0 = *(const float4*)&As[kk][ty * 8];
      float4 a1 = *(const float4*)&As[kk][ty * 8 + 4];
      float4 b4 = *(const float4*)&Bs[kk][tx * 4];
      float av[8] = {a0.x, a0.y, a0.z, a0.w, a1.x, a1.y, a1.z, a1.w};
      float bv[4] = {b4.x, b4.y, b4.z, b4.w};
#pragma unroll
      for (int i = 0; i < 8; i++)
#pragma unroll
        for (int j = 0; j < 4; j++) acc[i][j] = fmaf(av[i], bv[j], acc[i][j]);
    }
  }

#pragma unroll
  for (int i = 0; i < 8; i++) {
    const int q = q0 + ty * 8 + i;
    float4 o;
    o.x = acc[i][0]; o.y = acc[i][1]; o.z = acc[i][2]; o.w = acc[i][3];
    *(float4*)&g_ctx[((size_t)b * Sc + q) * Dc + h * DKc + tx * 4] = o;
  }
}

// ---------------------------------------------------------------------------
extern "C" void kernel_launch(void* const* d_in, const int* in_sizes, int n_in,
                              void* d_out, int out_size) {
  const float* in_q = (const float*)d_in[0];
  const float* in_k = (const float*)d_in[1];
  const float* in_v = (const float*)d_in[2];
  const int*   mask = (const int*)d_in[3];
  const float* prop = (const float*)d_in[4];
  const float* Wq = (const float*)d_in[5];
  const float* bq = (const float*)d_in[6];
  const float* Wk = (const float*)d_in[7];
  const float* bk = (const float*)d_in[8];
  const float* Wv = (const float*)d_in[9];
  const float* bv = (const float*)d_in[10];
  const float* Wo = (const float*)d_in[11];
  const float* bo = (const float*)d_in[12];
  float* out = (float*)d_out;

  float *qp, *kp, *vp, *ctxp;
  cudaGetSymbolAddress((void**)&qp, g_q);
  cudaGetSymbolAddress((void**)&kp, g_k);
  cudaGetSymbolAddress((void**)&vp, g_v);
  cudaGetSymbolAddress((void**)&ctxp, g_ctx);

  dim3 blk(256);
  dim3 gproj(1024 / 128, 4096 / 128);        // (8, 32)

  // 1) projections
  gemm_nn_bias<<<gproj, blk>>>(in_q, Wq, bq, qp);
  gemm_nn_bias<<<gproj, blk>>>(in_k, Wk, bk, kp);
  gemm_nn_bias<<<gproj, blk>>>(in_v, Wv, bv, vp);

  // 2) masked scaled QK^T
  dim3 gqk(Sc / 128, Sc / 128, BHc);         // (16, 16, 32)
  qk_mask_kernel<<<gqk, blk>>>(mask);

  // 3) attention propagation (dominant GEMM)
  dim3 gprop(Sc / 128, (BHc * Sc) / 128);    // (16, 512)
  prop_gemm_kernel<<<gprop, blk>>>(prop);

  // 4) masked softmax + nan_to_num
  softmax_kernel<<<BHc * Sc, 256>>>(mask);

  // 5) P @ V -> ctx in [b, q, h*dk] layout
  dim3 gav(1, Sc / 128, BHc);                // (1, 16, 32)
  av_kernel<<<gav, blk>>>();

  // 6) output projection
  gemm_nn_bias<<<gproj, blk>>>(ctxp, Wo, bo, out);
}

// round 12
// speedup vs baseline: 2.9146x; 2.9146x over previous
#include <cuda_runtime.h>
#include <cstdint>

// ---------------------------------------------------------------------------
// MultiHeadedAttention with attention-propagation.
//   B=2, S=2048, D=1024, H=16, DK=64
// R10: R9 design (mma.sync tf32 m16n8k8 + ldmatrix + 3-stage cp.async for the
//      549 GF prop GEMM) with the A-stage loader row stride fixed
//      (j*128 -> j*64; was reading/writing out of bounds).
// ---------------------------------------------------------------------------

#define Bc  2
#define Sc  2048
#define Dc  1024
#define Hc  16
#define DKc 64
#define BSc 4096           // B*S
#define BHc 32             // B*H

__device__ float g_q[BSc * Dc];
__device__ float g_k[BSc * Dc];
__device__ float g_v[BSc * Dc];
__device__ float g_ctx[BSc * Dc];
__device__ float g_p[Sc * Sc];      // tf32-rounded propagation matrix
__device__ float g_s1[134217728];   // [B*H, S, S]
__device__ float g_s2[134217728];

// =========================== PTX helpers ===================================
__device__ __forceinline__ uint32_t cvta_smem(const void* p) {
  uint32_t a;
  asm("{ .reg .u64 t; cvta.to.shared.u64 t, %1; cvt.u32.u64 %0, t; }"
      : "=r"(a) : "l"(p));
  return a;
}

#define CPA16(s, g)                                                            \
  asm volatile("cp.async.cg.shared.global [%0], [%1], 16;" :: "r"(s), "l"(g))
#define CP_COMMIT() asm volatile("cp.async.commit_group;" ::: "memory")
#define CP_WAIT1()  asm volatile("cp.async.wait_group 1;" ::: "memory")

#define LDSM_X4(r0, r1, r2, r3, addr)                                          \
  asm volatile("ldmatrix.sync.aligned.m8n8.x4.shared.b16 {%0,%1,%2,%3}, [%4];" \
               : "=r"(r0), "=r"(r1), "=r"(r2), "=r"(r3) : "r"(addr))

#define MMA_TF32(c0, c1, c2, c3, a0, a1, a2, a3, b0, b1)                       \
  asm volatile(                                                                \
      "mma.sync.aligned.m16n8k8.row.col.f32.tf32.tf32.f32 "                    \
      "{%0,%1,%2,%3}, {%4,%5,%6,%7}, {%8,%9}, {%0,%1,%2,%3};"                  \
      : "+f"(c0), "+f"(c1), "+f"(c2), "+f"(c3)                                 \
      : "r"(a0), "r"(a1), "r"(a2), "r"(a3), "r"(b0), "r"(b1))

__device__ __forceinline__ uint32_t sw128(uint32_t off) {
  return off ^ ((off >> 3) & 0x70);
}

// ================= mma.sync tf32 propagation GEMM ===========================
// S2[m,l] = sum_k S1[m,k] * P[l,k]  (NT; M=65536, N=2048, K=2048)
// CTA 512 thr = 16 warps (4M x 4N), tile M=256, N=128, K-chunk 32,
// 3-stage cp.async. Stage = A 256x32 f32 (32KB, SW128 rows) + B 128x32 (16KB).
#define PROP_STAGE_BYTES 49152
#define PROP_A_BYTES     32768
#define PROP_SMEM        (3 * PROP_STAGE_BYTES)   // 147456
#define PROP_NCHUNK      64

__device__ __forceinline__ void prop_load_stage(uint32_t sbase, const float* Ag,
                                                const float* Bg, int k0,
                                                int lr, int c4) {
  const uint32_t bbase = sbase + PROP_A_BYTES;
#pragma unroll
  for (int j = 0; j < 4; j++) {
    const int row = lr + j * 64;                 // 4 passes x 64 rows = 256
    CPA16(sbase + sw128((uint32_t)row * 128 + c4 * 16),
          Ag + (size_t)row * Sc + k0 + c4 * 4);
  }
#pragma unroll
  for (int j = 0; j < 2; j++) {
    const int row = lr + j * 64;                 // 2 passes x 64 rows = 128
    CPA16(bbase + sw128((uint32_t)row * 128 + c4 * 16),
          Bg + (size_t)row * Sc + k0 + c4 * 4);
  }
}

__global__ __launch_bounds__(512, 1) void prop_mma_kernel() {
  extern __shared__ char dsm[];
  const uint32_t smem_u = cvta_smem(dsm);

  const int tid = threadIdx.x;
  const int bm = blockIdx.y * 256;
  const int bn = blockIdx.x * 128;
  const int wid = tid >> 5, lane = tid & 31;
  const int wm = wid & 3;        // warp M index: rows wm*64..+64
  const int wn = wid >> 2;       // warp N index: cols wn*32..+32

  // cp.async thread mapping: 512 thr -> 64 rows x 8 float4 per pass
  const int lr = tid >> 3;
  const int c4 = tid & 7;

  const float* Ag = g_s1 + (size_t)bm * Sc;
  const float* Bg = g_p + (size_t)bn * Sc;

  float acc[4][4][4];            // [mi][nj][reg]
#pragma unroll
  for (int i = 0; i < 4; i++)
#pragma unroll
    for (int j = 0; j < 4; j++)
#pragma unroll
      for (int r = 0; r < 4; r++) acc[i][j][r] = 0.f;

  // ldmatrix lane addressing (within warp)
  const int lb = lane >> 3;      // matrix index 0..3
  const int lrw = lane & 7;      // row within matrix

  // A x4: matrices (rows+0,k+0),(rows+8,k+0),(rows+0,k+4),(rows+8,k+4)
  const uint32_t a_row_base = wm * 64 + (lb & 1) * 8 + lrw;   // + mi*16
  const uint32_t a_kc_off = (lb >> 1) * 4;                    // + ks*8
  // B x4: matrices (n+0,k+0),(n+0,k+4),(n+8,k+0),(n+8,k+4)
  const uint32_t b_row_base = wn * 32 + (lb >> 1) * 8 + lrw;  // + np*16
  const uint32_t b_kc_off = (lb & 1) * 4;                     // + ks*8

  // prologue
  prop_load_stage(smem_u, Ag, Bg, 0, lr, c4);
  CP_COMMIT();
  prop_load_stage(smem_u + PROP_STAGE_BYTES, Ag, Bg, 32, lr, c4);
  CP_COMMIT();

  for (int s = 0; s < PROP_NCHUNK; s++) {
    CP_WAIT1();
    __syncthreads();
    // prefetch stage s+2 into the buffer freed by compute(s-1)
    if (s + 2 < PROP_NCHUNK)
      prop_load_stage(smem_u + ((s + 2) % 3) * PROP_STAGE_BYTES, Ag, Bg,
                      (s + 2) * 32, lr, c4);
    CP_COMMIT();

    const uint32_t ab = smem_u + (s % 3) * PROP_STAGE_BYTES;
    const uint32_t bb = ab + PROP_A_BYTES;

#pragma unroll
    for (int ks = 0; ks < 4; ks++) {
      uint32_t af[4][4];
#pragma unroll
      for (int mi = 0; mi < 4; mi++) {
        const uint32_t addr = ab + sw128((a_row_base + mi * 16) * 128 +
                                         (ks * 8 + a_kc_off) * 4);
        LDSM_X4(af[mi][0], af[mi][1], af[mi][2], af[mi][3], addr);
      }
      uint32_t bf[4][2];
#pragma unroll
      for (int np = 0; np < 2; np++) {
        const uint32_t addr = bb + sw128((b_row_base + np * 16) * 128 +
                                         (ks * 8 + b_kc_off) * 4);
        uint32_t r0, r1, r2, r3;
        LDSM_X4(r0, r1, r2, r3, addr);
        bf[np * 2 + 0][0] = r0; bf[np * 2 + 0][1] = r1;
        bf[np * 2 + 1][0] = r2; bf[np * 2 + 1][1] = r3;
      }
#pragma unroll
      for (int mi = 0; mi < 4; mi++)
#pragma unroll
        for (int nj = 0; nj < 4; nj++)
          MMA_TF32(acc[mi][nj][0], acc[mi][nj][1], acc[mi][nj][2],
                   acc[mi][nj][3], af[mi][0], af[mi][1], af[mi][2], af[mi][3],
                   bf[nj][0], bf[nj][1]);
    }
  }

  // epilogue: c0,c1 -> (row g, col n2..n2+1); c2,c3 -> (row g+8, ...)
  const int g = lane >> 2, n2 = (lane & 3) * 2;
#pragma unroll
  for (int mi = 0; mi < 4; mi++) {
#pragma unroll
    for (int nj = 0; nj < 4; nj++) {
      const int row = bm + wm * 64 + mi * 16 + g;
      const int col = bn + wn * 32 + nj * 8 + n2;
      float2 lo, hi;
      lo.x = acc[mi][nj][0]; lo.y = acc[mi][nj][1];
      hi.x = acc[mi][nj][2]; hi.y = acc[mi][nj][3];
      *(float2*)(g_s2 + (size_t)row * Sc + col) = lo;
      *(float2*)(g_s2 + (size_t)(row + 8) * Sc + col) = hi;
    }
  }
}

// round P to tf32 (rna) so the tensor GEMM's truncation sees RN-rounded inputs
__global__ __launch_bounds__(256) void tf32_round_kernel(const float4* __restrict__ src,
                                                         float4* __restrict__ dst) {
  const int i = blockIdx.x * 256 + threadIdx.x;
  float4 v = src[i];
  uint32_t a, b, c, d;
  asm("cvt.rna.tf32.f32 %0, %1;" : "=r"(a) : "f"(v.x));
  asm("cvt.rna.tf32.f32 %0, %1;" : "=r"(b) : "f"(v.y));
  asm("cvt.rna.tf32.f32 %0, %1;" : "=r"(c) : "f"(v.z));
  asm("cvt.rna.tf32.f32 %0, %1;" : "=r"(d) : "f"(v.w));
  float4 o;
  o.x = __uint_as_float(a); o.y = __uint_as_float(b);
  o.z = __uint_as_float(c); o.w = __uint_as_float(d);
  dst[i] = o;
}

// =========================== SIMT kernels ===================================
template <int TK>
__device__ __forceinline__ void mm8x8(float (*As)[128], float (*Bs)[128],
                                      float (&acc)[8][8], int tx, int ty) {
#pragma unroll
  for (int kk = 0; kk < TK; kk++) {
    float4 a0 = *(const float4*)&As[kk][ty * 8];
    float4 a1 = *(const float4*)&As[kk][ty * 8 + 4];
    float4 b0 = *(const float4*)&Bs[kk][tx * 8];
    float4 b1 = *(const float4*)&Bs[kk][tx * 8 + 4];
    float av[8] = {a0.x, a0.y, a0.z, a0.w, a1.x, a1.y, a1.z, a1.w};
    float bv[8] = {b0.x, b0.y, b0.z, b0.w, b1.x, b1.y, b1.z, b1.w};
#pragma unroll
    for (int i = 0; i < 8; i++)
#pragma unroll
      for (int j = 0; j < 8; j++) acc[i][j] = fmaf(av[i], bv[j], acc[i][j]);
  }
}

__global__ __launch_bounds__(256, 2) void gemm_nn_bias(
    const float* __restrict__ A, const float* __restrict__ W,
    const float* __restrict__ bias, float* __restrict__ C) {
  const int N = 1024, K = 1024;
  __shared__ __align__(16) float As[8][128];
  __shared__ __align__(16) float Bs[8][128];
  const int bm = blockIdx.y * 128;
  const int bn = blockIdx.x * 128;
  const int tid = threadIdx.x;
  const int tx = tid & 15, ty = tid >> 4;
  const int ar = tid >> 1, ac = (tid & 1) * 4;
  const int wr = tid >> 5, wc = (tid & 31) * 4;
  float acc[8][8];
#pragma unroll
  for (int i = 0; i < 8; i++)
#pragma unroll
    for (int j = 0; j < 8; j++) acc[i][j] = 0.f;

  const float* Ap = A + (size_t)(bm + ar) * K + ac;
  const float* Wp = W + (size_t)wr * N + bn + wc;

  for (int k0 = 0; k0 < K; k0 += 8) {
    float4 av = *(const float4*)(Ap + k0);
    float4 wv = *(const float4*)(Wp + (size_t)k0 * N);
    __syncthreads();
    As[ac + 0][ar] = av.x; As[ac + 1][ar] = av.y;
    As[ac + 2][ar] = av.z; As[ac + 3][ar] = av.w;
    *(float4*)&Bs[wr][wc] = wv;
    __syncthreads();
    mm8x8<8>(As, Bs, acc, tx, ty);
  }

#pragma unroll
  for (int i = 0; i < 8; i++) {
    const int m = bm + ty * 8 + i;
#pragma unroll
    for (int j4 = 0; j4 < 2; j4++) {
      const int n = bn + tx * 8 + j4 * 4;
      float4 o;
      o.x = acc[i][j4 * 4 + 0] + bias[n + 0];
      o.y = acc[i][j4 * 4 + 1] + bias[n + 1];
      o.z = acc[i][j4 * 4 + 2] + bias[n + 2];
      o.w = acc[i][j4 * 4 + 3] + bias[n + 3];
      *(float4*)&C[(size_t)m * N + n] = o;
    }
  }
}

__global__ __launch_bounds__(256, 2) void qk_mask_kernel(const int* __restrict__ mask) {
  const int bh = blockIdx.z;
  const int b = bh >> 4, h = bh & 15;
  const int q0 = blockIdx.y * 128;
  const int n0 = blockIdx.x * 128;
  __shared__ __align__(16) float As[16][128];
  __shared__ __align__(16) float Bs[16][128];
  const int tid = threadIdx.x;
  const int tx = tid & 15, ty = tid >> 4;
  const int idx = tid * 2;
  const int r = idx >> 2;
  const int c0 = (idx & 3) * 4;
  const int c1 = c0 + 4;

  const float* Qb = g_q + ((size_t)b * Sc + q0) * Dc + h * DKc;
  const float* Kb = g_k + ((size_t)b * Sc + n0) * Dc + h * DKc;

  float acc[8][8];
#pragma unroll
  for (int i = 0; i < 8; i++)
#pragma unroll
    for (int j = 0; j < 8; j++) acc[i][j] = 0.f;

  for (int kc = 0; kc < DKc; kc += 16) {
    float4 qa = *(const float4*)(Qb + (size_t)r * Dc + kc + c0);
    float4 qd = *(const float4*)(Qb + (size_t)r * Dc + kc + c1);
    float4 ka = *(const float4*)(Kb + (size_t)r * Dc + kc + c0);
    float4 kd = *(const float4*)(Kb + (size_t)r * Dc + kc + c1);
    __syncthreads();
    As[c0 + 0][r] = qa.x; As[c0 + 1][r] = qa.y; As[c0 + 2][r] = qa.z; As[c0 + 3][r] = qa.w;
    As[c1 + 0][r] = qd.x; As[c1 + 1][r] = qd.y; As[c1 + 2][r] = qd.z; As[c1 + 3][r] = qd.w;
    Bs[c0 + 0][r] = ka.x; Bs[c0 + 1][r] = ka.y; Bs[c0 + 2][r] = ka.z; Bs[c0 + 3][r] = ka.w;
    Bs[c1 + 0][r] = kd.x; Bs[c1 + 1][r] = kd.y; Bs[c1 + 2][r] = kd.z; Bs[c1 + 3][r] = kd.w;
    __syncthreads();
    mm8x8<16>(As, Bs, acc, tx, ty);
  }

#pragma unroll
  for (int i = 0; i < 8; i++) {
    const int m = q0 + ty * 8 + i;
    const size_t mrow = ((size_t)b * Sc + m) * Sc;
    const size_t orow = ((size_t)bh * Sc + m) * Sc;
#pragma unroll
    for (int j = 0; j < 8; j++) {
      const int n = n0 + tx * 8 + j;
      float val = mask[mrow + n] ? acc[i][j] * 0.125f : 0.f;
      uint32_t t;  // rna-round to tf32 so the tensor GEMM sees RN inputs
      asm("cvt.rna.tf32.f32 %0, %1;" : "=r"(t) : "f"(val));
      g_s1[orow + n] = __uint_as_float(t);
    }
  }
}

__global__ __launch_bounds__(256) void softmax_kernel(const int* __restrict__ mask) {
  const int row = blockIdx.x;
  const int b = row >> 15;
  const int q = row & (Sc - 1);
  float* p = g_s2 + (size_t)row * Sc;
  const int* mrow = mask + ((size_t)b * Sc + q) * Sc;
  const int tid = threadIdx.x;
  __shared__ float red[256];

  float mx = -3.402823466e38f;
  for (int i = tid; i < Sc; i += 256)
    if (mrow[i]) mx = fmaxf(mx, p[i]);
  red[tid] = mx;
  __syncthreads();
  for (int s = 128; s > 0; s >>= 1) {
    if (tid < s) red[tid] = fmaxf(red[tid], red[tid + s]);
    __syncthreads();
  }
  mx = red[0];
  __syncthreads();

  float sum = 0.f;
  for (int i = tid; i < Sc; i += 256) {
    float e = mrow[i] ? expf(p[i] - mx) : 0.f;
    p[i] = e;
    sum += e;
  }
  red[tid] = sum;
  __syncthreads();
  for (int s = 128; s > 0; s >>= 1) {
    if (tid < s) red[tid] += red[tid + s];
    __syncthreads();
  }
  const float inv = red[0] > 0.f ? 1.f / red[0] : 0.f;
  for (int i = tid; i < Sc; i += 256) p[i] *= inv;
}

__global__ __launch_bounds__(256, 2) void av_kernel() {
  const int bh = blockIdx.z;
  const int b = bh >> 4, h = bh & 15;
  const int q0 = blockIdx.y * 128;
  __shared__ __align__(16) float As[16][128];
  __shared__ __align__(16) float Bs[16][64];
  const int tid = threadIdx.x;
  const int tx = tid & 15, ty = tid >> 4;
  const int idx = tid * 2;
  const int r = idx >> 2;
  const int c0 = (idx & 3) * 4;
  const int c1 = c0 + 4;
  const int vr = tid >> 4, vc = (tid & 15) * 4;

  const float* Pb = g_s2 + ((size_t)bh * Sc + q0) * Sc;
  const float* Vb = g_v + (size_t)b * Sc * Dc + h * DKc;

  float acc[8][4];
#pragma unroll
  for (int i = 0; i < 8; i++)
#pragma unroll
    for (int j = 0; j < 4; j++) acc[i][j] = 0.f;

  for (int l0 = 0; l0 < Sc; l0 += 16) {
    float4 pa = *(const float4*)(Pb + (size_t)r * Sc + l0 + c0);
    float4 pd = *(const float4*)(Pb + (size_t)r * Sc + l0 + c1);
    float4 vv = *(const float4*)(Vb + (size_t)(l0 + vr) * Dc + vc);
    __syncthreads();
    As[c0 + 0][r] = pa.x; As[c0 + 1][r] = pa.y; As[c0 + 2][r] = pa.z; As[c0 + 3][r] = pa.w;
    As[c1 + 0][r] = pd.x; As[c1 + 1][r] = pd.y; As[c1 + 2][r] = pd.z; As[c1 + 3][r] = pd.w;
    *(float4*)&Bs[vr][vc] = vv;
    __syncthreads();
#pragma unroll
    for (int kk = 0; kk < 16; kk++) {
      float4 a0 = *(const float4*)&As[kk][ty * 8];
      float4 a1 = *(const float4*)&As[kk][ty * 8 + 4];
      float4 b4 = *(const float4*)&Bs[kk][tx * 4];
      float av[8] = {a0.x, a0.y, a0.z, a0.w, a1.x, a1.y, a1.z, a1.w};
      float bv[4] = {b4.x, b4.y, b4.z, b4.w};
#pragma unroll
      for (int i = 0; i < 8; i++)
#pragma unroll
        for (int j = 0; j < 4; j++) acc[i][j] = fmaf(av[i], bv[j], acc[i][j]);
    }
  }

#pragma unroll
  for (int i = 0; i < 8; i++) {
    const int q = q0 + ty * 8 + i;
    float4 o;
    o.x = acc[i][0]; o.y = acc[i][1]; o.z = acc[i][2]; o.w = acc[i][3];
    *(float4*)&g_ctx[((size_t)b * Sc + q) * Dc + h * DKc + tx * 4] = o;
  }
}

// ---------------------------------------------------------------------------
extern "C" void kernel_launch(void* const* d_in, const int* in_sizes, int n_in,
                              void* d_out, int out_size) {
  const float* in_q = (const float*)d_in[0];
  const float* in_k = (const float*)d_in[1];
  const float* in_v = (const float*)d_in[2];
  const int*   mask = (const int*)d_in[3];
  const float* prop = (const float*)d_in[4];
  const float* Wq = (const float*)d_in[5];
  const float* bq = (const float*)d_in[6];
  const float* Wk = (const float*)d_in[7];
  const float* bk = (const float*)d_in[8];
  const float* Wv = (const float*)d_in[9];
  const float* bv = (const float*)d_in[10];
  const float* Wo = (const float*)d_in[11];
  const float* bo = (const float*)d_in[12];
  float* out = (float*)d_out;

  float *qp, *kp, *vp, *ctxp, *pp;
  cudaGetSymbolAddress((void**)&qp, g_q);
  cudaGetSymbolAddress((void**)&kp, g_k);
  cudaGetSymbolAddress((void**)&vp, g_v);
  cudaGetSymbolAddress((void**)&ctxp, g_ctx);
  cudaGetSymbolAddress((void**)&pp, g_p);

  cudaFuncSetAttribute(prop_mma_kernel,
                       cudaFuncAttributeMaxDynamicSharedMemorySize, PROP_SMEM);

  dim3 blk(256);
  dim3 gproj(1024 / 128, 4096 / 128);

  // 1) projections
  gemm_nn_bias<<<gproj, blk>>>(in_q, Wq, bq, qp);
  gemm_nn_bias<<<gproj, blk>>>(in_k, Wk, bk, kp);
  gemm_nn_bias<<<gproj, blk>>>(in_v, Wv, bv, vp);

  // 2) masked scaled QK^T (tf32-rounded output)
  dim3 gqk(Sc / 128, Sc / 128, BHc);
  qk_mask_kernel<<<gqk, blk>>>(mask);

  // 3) attention propagation on mma.sync tf32
  tf32_round_kernel<<<(Sc * Sc / 4) / 256, 256>>>((const float4*)prop, (float4*)pp);
  dim3 gprop(Sc / 128, (BHc * Sc) / 256);   // (16, 256): n fast -> B reuse in L2
  prop_mma_kernel<<<gprop, dim3(512), PROP_SMEM>>>();

  // 4) masked softmax + nan_to_num
  softmax_kernel<<<BHc * Sc, 256>>>(mask);

  // 5) P @ V
  dim3 gav(1, Sc / 128, BHc);
  av_kernel<<<gav, blk>>>();

  // 6) output projection
  gemm_nn_bias<<<gproj, blk>>>(ctxp, Wo, bo, out);
}

// round 13
// speedup vs baseline: 4.2611x; 1.4620x over previous
#include <cuda_runtime.h>
#include <cstdint>

// ---------------------------------------------------------------------------
// MultiHeadedAttention with attention-propagation.
//   B=2, S=2048, D=1024, H=16, DK=64
// R13: all five GEMMs on mma.sync tf32 (m16n8k8 + ldmatrix + cp.async
//      pipeline), via a shared templated mainloop. cp.async group-accounting
//      race fixed (no empty commits; wait_group 0 on last chunk).
// ---------------------------------------------------------------------------

#define Bc  2
#define Sc  2048
#define Dc  1024
#define Hc  16
#define DKc 64
#define BSc 4096           // B*S
#define BHc 32             // B*H

__device__ float g_q[BSc * Dc];
__device__ float g_k[BSc * Dc];
__device__ float g_v[BSc * Dc];
__device__ float g_ctx[BSc * Dc];
__device__ float g_p[Sc * Sc];        // tf32-rounded propagation matrix
__device__ float g_wt[4 * Dc * Dc];   // transposed+rounded Wq,Wk,Wv,Wo
__device__ float g_vt[BHc * DKc * Sc];// per-(b,h) transposed+rounded V
__device__ float g_s1[134217728];     // [B*H, S, S]; head also reused as
                                      // rounded-input scratch pre-qk
__device__ float g_s2[134217728];

// =========================== PTX helpers ===================================
__device__ __forceinline__ uint32_t cvta_smem(const void* p) {
  uint32_t a;
  asm("{ .reg .u64 t; cvta.to.shared.u64 t, %1; cvt.u32.u64 %0, t; }"
      : "=r"(a) : "l"(p));
  return a;
}

#define CPA16(s, g)                                                            \
  asm volatile("cp.async.cg.shared.global [%0], [%1], 16;" :: "r"(s), "l"(g))
#define CP_COMMIT() asm volatile("cp.async.commit_group;" ::: "memory")
#define CP_WAIT1()  asm volatile("cp.async.wait_group 1;" ::: "memory")
#define CP_WAIT0()  asm volatile("cp.async.wait_group 0;" ::: "memory")

#define LDSM_X4(r0, r1, r2, r3, addr)                                          \
  asm volatile("ldmatrix.sync.aligned.m8n8.x4.shared.b16 {%0,%1,%2,%3}, [%4];" \
               : "=r"(r0), "=r"(r1), "=r"(r2), "=r"(r3) : "r"(addr))

#define MMA_TF32(c0, c1, c2, c3, a0, a1, a2, a3, b0, b1)                       \
  asm volatile(                                                                \
      "mma.sync.aligned.m16n8k8.row.col.f32.tf32.tf32.f32 "                    \
      "{%0,%1,%2,%3}, {%4,%5,%6,%7}, {%8,%9}, {%0,%1,%2,%3};"                  \
      : "+f"(c0), "+f"(c1), "+f"(c2), "+f"(c3)                                 \
      : "r"(a0), "r"(a1), "r"(a2), "r"(a3), "r"(b0), "r"(b1))

__device__ __forceinline__ uint32_t sw128(uint32_t off) {
  return off ^ ((off >> 3) & 0x70);
}

__device__ __forceinline__ float rna_tf32(float x) {
  uint32_t t;
  asm("cvt.rna.tf32.f32 %0, %1;" : "=r"(t) : "f"(x));
  return __uint_as_float(t);
}

// ================= shared NT mma.sync tf32 mainloop ========================
// C[256, BN] += A[256, 32*NCHUNK] * B[BN, 32*NCHUNK]^T   (both K-major)
// A tile fixed 256 rows; B tile BROWS rows; K-chunk 32; SW128 smem rows.
// Warps: wm = wid&3 (M 64/warp), wn = wid>>5... wn = wid>>2 (N 32/warp).

template <int NTHREADS, int BROWS>
__device__ __forceinline__ void load_stage(uint32_t sbase, const float* Ag,
                                           int lda, const float* Bg, int ldb,
                                           int k0, int lr, int c4) {
  constexpr int RPP = NTHREADS / 8;          // rows per pass
  const uint32_t bbase = sbase + 32768;
#pragma unroll
  for (int j = 0; j < 256 / RPP; j++) {
    const int row = lr + j * RPP;
    CPA16(sbase + sw128((uint32_t)row * 128 + c4 * 16),
          Ag + (size_t)row * lda + k0 + c4 * 4);
  }
#pragma unroll
  for (int j = 0; j < BROWS / RPP; j++) {
    const int row = lr + j * RPP;
    CPA16(bbase + sw128((uint32_t)row * 128 + c4 * 16),
          Bg + (size_t)row * ldb + k0 + c4 * 4);
  }
}

template <int NTHREADS, int BROWS, int NCHUNK, int NSTAGES>
__device__ __forceinline__ void mma_mainloop(uint32_t smem_u, const float* Ag,
                                             int lda, const float* Bg, int ldb,
                                             float (&acc)[4][4][4]) {
  constexpr uint32_t STAGE = 32768u + BROWS * 128u;
  const int tid = threadIdx.x;
  const int lane = tid & 31, wid = tid >> 5;
  const int wm = wid & 3, wn = wid >> 2;
  const int lr = tid >> 3, c4 = tid & 7;
  const int lb = lane >> 3, lrw = lane & 7;

  // validated fragment addressing (R10/R12)
  const uint32_t a_row_base = wm * 64 + (lb & 1) * 8 + lrw;   // + mi*16
  const uint32_t a_kc_off = (lb >> 1) * 4;                    // + ks*8
  const uint32_t b_row_base = wn * 32 + (lb >> 1) * 8 + lrw;  // + np*16
  const uint32_t b_kc_off = (lb & 1) * 4;                     // + ks*8

  load_stage<NTHREADS, BROWS>(smem_u, Ag, lda, Bg, ldb, 0, lr, c4);
  CP_COMMIT();
  if (NCHUNK > 1) {
    load_stage<NTHREADS, BROWS>(smem_u + STAGE, Ag, lda, Bg, ldb, 32, lr, c4);
    CP_COMMIT();
  }

  for (int s = 0; s < NCHUNK; s++) {
    if (s + 1 < NCHUNK) CP_WAIT1(); else CP_WAIT0();
    __syncthreads();
    if (s + 2 < NCHUNK) {  // only real groups get committed
      load_stage<NTHREADS, BROWS>(smem_u + ((s + 2) % NSTAGES) * STAGE, Ag,
                                  lda, Bg, ldb, (s + 2) * 32, lr, c4);
      CP_COMMIT();
    }

    const uint32_t ab = smem_u + (s % NSTAGES) * STAGE;
    const uint32_t bb = ab + 32768;

#pragma unroll
    for (int ks = 0; ks < 4; ks++) {
      uint32_t af[4][4];
#pragma unroll
      for (int mi = 0; mi < 4; mi++) {
        const uint32_t addr = ab + sw128((a_row_base + mi * 16) * 128 +
                                         (ks * 8 + a_kc_off) * 4);
        LDSM_X4(af[mi][0], af[mi][1], af[mi][2], af[mi][3], addr);
      }
      uint32_t bf[4][2];
#pragma unroll
      for (int np = 0; np < 2; np++) {
        const uint32_t addr = bb + sw128((b_row_base + np * 16) * 128 +
                                         (ks * 8 + b_kc_off) * 4);
        uint32_t r0, r1, r2, r3;
        LDSM_X4(r0, r1, r2, r3, addr);
        bf[np * 2 + 0][0] = r0; bf[np * 2 + 0][1] = r1;
        bf[np * 2 + 1][0] = r2; bf[np * 2 + 1][1] = r3;
      }
#pragma unroll
      for (int mi = 0; mi < 4; mi++)
#pragma unroll
        for (int nj = 0; nj < 4; nj++)
          MMA_TF32(acc[mi][nj][0], acc[mi][nj][1], acc[mi][nj][2],
                   acc[mi][nj][3], af[mi][0], af[mi][1], af[mi][2], af[mi][3],
                   bf[nj][0], bf[nj][1]);
    }
  }
}

#define ACC_INIT(acc)                                                          \
  _Pragma("unroll") for (int i = 0; i < 4; i++)                                \
  _Pragma("unroll") for (int j = 0; j < 4; j++)                                \
  _Pragma("unroll") for (int r = 0; r < 4; r++) acc[i][j][r] = 0.f

// ===================== kernel: projections (NN via Wt) ======================
// C[4096,1024] = A[4096,1024] @ Wt[1024(n),1024(k)]^T + bias
#define PROJ_SMEM (3 * 49152)
template <bool ROUND>
__global__ __launch_bounds__(512, 1) void proj_mma_kernel(
    const float* __restrict__ A, const float* __restrict__ Wt,
    const float* __restrict__ bias, float* __restrict__ C) {
  extern __shared__ char dsm[];
  const uint32_t smem_u = cvta_smem(dsm);
  const int bm = blockIdx.y * 256, bn = blockIdx.x * 128;

  float acc[4][4][4];
  ACC_INIT(acc);
  mma_mainloop<512, 128, 32, 3>(smem_u, A + (size_t)bm * Dc, Dc,
                                Wt + (size_t)bn * Dc, Dc, acc);

  const int lane = threadIdx.x & 31, wid = threadIdx.x >> 5;
  const int wm = wid & 3, wn = wid >> 2;
  const int g = lane >> 2, n2 = (lane & 3) * 2;
#pragma unroll
  for (int mi = 0; mi < 4; mi++)
#pragma unroll
    for (int nj = 0; nj < 4; nj++) {
      const int row = bm + wm * 64 + mi * 16 + g;
      const int col = bn + wn * 32 + nj * 8 + n2;
      const float b0 = bias[col], b1 = bias[col + 1];
      float2 lo, hi;
      lo.x = acc[mi][nj][0] + b0; lo.y = acc[mi][nj][1] + b1;
      hi.x = acc[mi][nj][2] + b0; hi.y = acc[mi][nj][3] + b1;
      if (ROUND) {
        lo.x = rna_tf32(lo.x); lo.y = rna_tf32(lo.y);
        hi.x = rna_tf32(hi.x); hi.y = rna_tf32(hi.y);
      }
      *(float2*)(C + (size_t)row * Dc + col) = lo;
      *(float2*)(C + (size_t)(row + 8) * Dc + col) = hi;
    }
}

// ===================== kernel: masked scaled QK^T ===========================
// S1[bh,q,n] = mask[b,0,q,n] ? (Q.K)/8 : 0, rounded to tf32.  K=64.
#define QK_SMEM (2 * 49152)
__global__ __launch_bounds__(512, 1) void qk_mma_kernel(
    const int* __restrict__ mask) {
  extern __shared__ char dsm[];
  const uint32_t smem_u = cvta_smem(dsm);
  const int bh = blockIdx.z;
  const int b = bh >> 4, h = bh & 15;
  const int bm = blockIdx.y * 256, bn = blockIdx.x * 128;

  float acc[4][4][4];
  ACC_INIT(acc);
  mma_mainloop<512, 128, 2, 2>(smem_u,
                               g_q + ((size_t)b * Sc + bm) * Dc + h * DKc, Dc,
                               g_k + ((size_t)b * Sc + bn) * Dc + h * DKc, Dc,
                               acc);

  const int lane = threadIdx.x & 31, wid = threadIdx.x >> 5;
  const int wm = wid & 3, wn = wid >> 2;
  const int g = lane >> 2, n2 = (lane & 3) * 2;
#pragma unroll
  for (int mi = 0; mi < 4; mi++)
#pragma unroll
    for (int nj = 0; nj < 4; nj++) {
      const int row = bm + wm * 64 + mi * 16 + g;
      const int col = bn + wn * 32 + nj * 8 + n2;
      const size_t m0 = ((size_t)b * Sc + row) * Sc + col;
      const size_t m1 = ((size_t)b * Sc + row + 8) * Sc + col;
      const int2 mk0 = *(const int2*)(mask + m0);
      const int2 mk1 = *(const int2*)(mask + m1);
      float2 lo, hi;
      lo.x = mk0.x ? rna_tf32(acc[mi][nj][0] * 0.125f) : 0.f;
      lo.y = mk0.y ? rna_tf32(acc[mi][nj][1] * 0.125f) : 0.f;
      hi.x = mk1.x ? rna_tf32(acc[mi][nj][2] * 0.125f) : 0.f;
      hi.y = mk1.y ? rna_tf32(acc[mi][nj][3] * 0.125f) : 0.f;
      *(float2*)(g_s1 + ((size_t)bh * Sc + row) * Sc + col) = lo;
      *(float2*)(g_s1 + ((size_t)bh * Sc + row + 8) * Sc + col) = hi;
    }
}

// ===================== kernel: propagation GEMM =============================
// S2[m,l] = sum_k S1[m,k] * P[l,k]   (M=65536, N=2048, K=2048)
#define PROP_SMEM (3 * 49152)
__global__ __launch_bounds__(512, 1) void prop_mma_kernel() {
  extern __shared__ char dsm[];
  const uint32_t smem_u = cvta_smem(dsm);
  const int bm = blockIdx.y * 256, bn = blockIdx.x * 128;

  float acc[4][4][4];
  ACC_INIT(acc);
  mma_mainloop<512, 128, 64, 3>(smem_u, g_s1 + (size_t)bm * Sc, Sc,
                                g_p + (size_t)bn * Sc, Sc, acc);

  const int lane = threadIdx.x & 31, wid = threadIdx.x >> 5;
  const int wm = wid & 3, wn = wid >> 2;
  const int g = lane >> 2, n2 = (lane & 3) * 2;
#pragma unroll
  for (int mi = 0; mi < 4; mi++)
#pragma unroll
    for (int nj = 0; nj < 4; nj++) {
      const int row = bm + wm * 64 + mi * 16 + g;
      const int col = bn + wn * 32 + nj * 8 + n2;
      float2 lo, hi;
      lo.x = acc[mi][nj][0]; lo.y = acc[mi][nj][1];
      hi.x = acc[mi][nj][2]; hi.y = acc[mi][nj][3];
      *(float2*)(g_s2 + (size_t)row * Sc + col) = lo;
      *(float2*)(g_s2 + (size_t)(row + 8) * Sc + col) = hi;
    }
}

// ===================== kernel: P @ V (per head) =============================
// ctx[b,q,h,:] = sum_l S2[bh,q,l] * Vt[bh,d,l].  M=2048, N=64, K=2048.
#define AV_SMEM (3 * 40960)
__global__ __launch_bounds__(256, 1) void av_mma_kernel() {
  extern __shared__ char dsm[];
  const uint32_t smem_u = cvta_smem(dsm);
  const int bh = blockIdx.z;
  const int b = bh >> 4, h = bh & 15;
  const int bm = blockIdx.y * 256;

  float acc[4][4][4];
  ACC_INIT(acc);
  mma_mainloop<256, 64, 64, 3>(smem_u, g_s2 + ((size_t)bh * Sc + bm) * Sc, Sc,
                               g_vt + (size_t)bh * DKc * Sc, Sc, acc);

  const int lane = threadIdx.x & 31, wid = threadIdx.x >> 5;
  const int wm = wid & 3, wn = wid >> 2;   // wn in {0,1}
  const int g = lane >> 2, n2 = (lane & 3) * 2;
#pragma unroll
  for (int mi = 0; mi < 4; mi++)
#pragma unroll
    for (int nj = 0; nj < 4; nj++) {
      const int row = bm + wm * 64 + mi * 16 + g;
      const int col = wn * 32 + nj * 8 + n2;   // 0..63
      float2 lo, hi;
      lo.x = rna_tf32(acc[mi][nj][0]); lo.y = rna_tf32(acc[mi][nj][1]);
      hi.x = rna_tf32(acc[mi][nj][2]); hi.y = rna_tf32(acc[mi][nj][3]);
      *(float2*)(g_ctx + ((size_t)b * Sc + row) * Dc + h * DKc + col) = lo;
      *(float2*)(g_ctx + ((size_t)b * Sc + row + 8) * Dc + h * DKc + col) = hi;
    }
}

// ====================== transposes and rounding =============================
__global__ __launch_bounds__(1024) void transpose_w_kernel(
    const float* __restrict__ W, float* __restrict__ Wt) {
  __shared__ float t[32][33];
  const int tx = threadIdx.x, ty = threadIdx.y;
  const int n0 = blockIdx.x * 32, k0 = blockIdx.y * 32;
  t[ty][tx] = W[(size_t)(k0 + ty) * Dc + n0 + tx];
  __syncthreads();
  Wt[(size_t)(n0 + ty) * Dc + k0 + tx] = rna_tf32(t[tx][ty]);
}

__global__ __launch_bounds__(1024) void transpose_v_kernel() {
  __shared__ float t[32][33];
  const int tx = threadIdx.x, ty = threadIdx.y;
  const int bh = blockIdx.z;
  const int b = bh >> 4, h = bh & 15;
  const int l0 = blockIdx.x * 32, d0 = blockIdx.y * 32;
  t[ty][tx] = g_v[((size_t)b * Sc + l0 + ty) * Dc + h * DKc + d0 + tx];
  __syncthreads();
  g_vt[(size_t)bh * DKc * Sc + (size_t)(d0 + ty) * Sc + l0 + tx] =
      rna_tf32(t[tx][ty]);
}

__global__ __launch_bounds__(256) void tf32_round_kernel(
    const float4* __restrict__ src, float4* __restrict__ dst) {
  const int i = blockIdx.x * 256 + threadIdx.x;
  float4 v = src[i];
  float4 o;
  o.x = rna_tf32(v.x); o.y = rna_tf32(v.y);
  o.z = rna_tf32(v.z); o.w = rna_tf32(v.w);
  dst[i] = o;
}

// ========================= masked softmax ===================================
__global__ __launch_bounds__(256) void softmax_kernel(const int* __restrict__ mask) {
  const int row = blockIdx.x;           // (b*H+h)*S + q
  const int b = row >> 15;
  const int q = row & (Sc - 1);
  float* p = g_s2 + (size_t)row * Sc;
  const int* mrow = mask + ((size_t)b * Sc + q) * Sc;
  const int tid = threadIdx.x;
  __shared__ float red[256];

  float mx = -3.402823466e38f;
  for (int i = tid; i < Sc; i += 256)
    if (mrow[i]) mx = fmaxf(mx, p[i]);
  red[tid] = mx;
  __syncthreads();
  for (int s = 128; s > 0; s >>= 1) {
    if (tid < s) red[tid] = fmaxf(red[tid], red[tid + s]);
    __syncthreads();
  }
  mx = red[0];
  __syncthreads();

  float sum = 0.f;
  for (int i = tid; i < Sc; i += 256) {
    float e = mrow[i] ? expf(p[i] - mx) : 0.f;
    p[i] = e;
    sum += e;
  }
  red[tid] = sum;
  __syncthreads();
  for (int s = 128; s > 0; s >>= 1) {
    if (tid < s) red[tid] += red[tid + s];
    __syncthreads();
  }
  const float inv = red[0] > 0.f ? 1.f / red[0] : 0.f;  // nan_to_num
  for (int i = tid; i < Sc; i += 256) p[i] = rna_tf32(p[i] * inv);
}

// ---------------------------------------------------------------------------
extern "C" void kernel_launch(void* const* d_in, const int* in_sizes, int n_in,
                              void* d_out, int out_size) {
  const float* in_q = (const float*)d_in[0];
  const float* in_k = (const float*)d_in[1];
  const float* in_v = (const float*)d_in[2];
  const int*   mask = (const int*)d_in[3];
  const float* prop = (const float*)d_in[4];
  const float* Wq = (const float*)d_in[5];
  const float* bq = (const float*)d_in[6];
  const float* Wk = (const float*)d_in[7];
  const float* bk = (const float*)d_in[8];
  const float* Wv = (const float*)d_in[9];
  const float* bv = (const float*)d_in[10];
  const float* Wo = (const float*)d_in[11];
  const float* bo = (const float*)d_in[12];
  float* out = (float*)d_out;

  float *qp, *kp, *vp, *ctxp, *pp, *wtp, *s1p;
  cudaGetSymbolAddress((void**)&qp, g_q);
  cudaGetSymbolAddress((void**)&kp, g_k);
  cudaGetSymbolAddress((void**)&vp, g_v);
  cudaGetSymbolAddress((void**)&ctxp, g_ctx);
  cudaGetSymbolAddress((void**)&pp, g_p);
  cudaGetSymbolAddress((void**)&wtp, g_wt);
  cudaGetSymbolAddress((void**)&s1p, g_s1);

  cudaFuncSetAttribute(proj_mma_kernel<true>,
                       cudaFuncAttributeMaxDynamicSharedMemorySize, PROJ_SMEM);
  cudaFuncSetAttribute(proj_mma_kernel<false>,
                       cudaFuncAttributeMaxDynamicSharedMemorySize, PROJ_SMEM);
  cudaFuncSetAttribute(qk_mma_kernel,
                       cudaFuncAttributeMaxDynamicSharedMemorySize, QK_SMEM);
  cudaFuncSetAttribute(prop_mma_kernel,
                       cudaFuncAttributeMaxDynamicSharedMemorySize, PROP_SMEM);
  cudaFuncSetAttribute(av_mma_kernel,
                       cudaFuncAttributeMaxDynamicSharedMemorySize, AV_SMEM);

  const int XN = BSc * Dc;               // 4,194,304 elems per input
  float* xq = s1p;                       // rounded-input scratch lives in the
  float* xk = s1p + XN;                  // head of g_s1 (dead until qk writes)
  float* xv = s1p + 2 * XN;
  float* wt0 = wtp, *wt1 = wtp + Dc * Dc, *wt2 = wtp + 2 * Dc * Dc,
        *wt3 = wtp + 3 * Dc * Dc;

  // 0) round inputs to tf32; transpose+round weights
  tf32_round_kernel<<<XN / 1024, 256>>>((const float4*)in_q, (float4*)xq);
  tf32_round_kernel<<<XN / 1024, 256>>>((const float4*)in_k, (float4*)xk);
  tf32_round_kernel<<<XN / 1024, 256>>>((const float4*)in_v, (float4*)xv);
  dim3 tb(32, 32);
  transpose_w_kernel<<<dim3(32, 32), tb>>>(Wq, wt0);
  transpose_w_kernel<<<dim3(32, 32), tb>>>(Wk, wt1);
  transpose_w_kernel<<<dim3(32, 32), tb>>>(Wv, wt2);
  transpose_w_kernel<<<dim3(32, 32), tb>>>(Wo, wt3);

  // 1) projections (Q/K rounded for qk mma; V rounded in transpose_v)
  dim3 gproj(Dc / 128, BSc / 256);       // (8, 16)
  proj_mma_kernel<true><<<gproj, 512, PROJ_SMEM>>>(xq, wt0, bq, qp);
  proj_mma_kernel<true><<<gproj, 512, PROJ_SMEM>>>(xk, wt1, bk, kp);
  proj_mma_kernel<false><<<gproj, 512, PROJ_SMEM>>>(xv, wt2, bv, vp);
  transpose_v_kernel<<<dim3(Sc / 32, DKc / 32, BHc), tb>>>();

  // 2) masked scaled QK^T
  qk_mma_kernel<<<dim3(Sc / 128, Sc / 256, BHc), 512, QK_SMEM>>>(mask);

  // 3) attention propagation (dominant)
  tf32_round_kernel<<<(Sc * Sc) / 1024, 256>>>((const float4*)prop, (float4*)pp);
  prop_mma_kernel<<<dim3(Sc / 128, (BHc * Sc) / 256), 512, PROP_SMEM>>>();

  // 4) masked softmax + nan_to_num (rounds P for av mma)
  softmax_kernel<<<BHc * Sc, 256>>>(mask);

  // 5) P @ V
  av_mma_kernel<<<dim3(1, Sc / 256, BHc), 256, AV_SMEM>>>();

  // 6) output projection
  proj_mma_kernel<false><<<gproj, 512, PROJ_SMEM>>>(ctxp, wt3, bo, out);
}

// round 16
// speedup vs baseline: 4.9918x; 1.1715x over previous
#include <cuda_runtime.h>
#include <cstdint>

// ---------------------------------------------------------------------------
// MultiHeadedAttention with attention-propagation.
//   B=2, S=2048, D=1024, H=16, DK=64
// R14: prop GEMM moved to 256-thr / 128x128-tile / 96KB-smem config for
//      occupancy 2 (bubble filling); softmax rewritten single-pass with
//      register-cached row. All mma.sync tf32 machinery from R13 kept.
// ---------------------------------------------------------------------------

#define Bc  2
#define Sc  2048
#define Dc  1024
#define Hc  16
#define DKc 64
#define BSc 4096           // B*S
#define BHc 32             // B*H

__device__ float g_q[BSc * Dc];
__device__ float g_k[BSc * Dc];
__device__ float g_v[BSc * Dc];
__device__ float g_ctx[BSc * Dc];
__device__ float g_p[Sc * Sc];        // tf32-rounded propagation matrix
__device__ float g_wt[4 * Dc * Dc];   // transposed+rounded Wq,Wk,Wv,Wo
__device__ float g_vt[BHc * DKc * Sc];// per-(b,h) transposed+rounded V
__device__ float g_s1[134217728];     // [B*H, S, S]; head also reused as
                                      // rounded-input scratch pre-qk
__device__ float g_s2[134217728];

// =========================== PTX helpers ===================================
__device__ __forceinline__ uint32_t cvta_smem(const void* p) {
  uint32_t a;
  asm("{ .reg .u64 t; cvta.to.shared.u64 t, %1; cvt.u32.u64 %0, t; }"
      : "=r"(a) : "l"(p));
  return a;
}

#define CPA16(s, g)                                                            \
  asm volatile("cp.async.cg.shared.global [%0], [%1], 16;" :: "r"(s), "l"(g))
#define CP_COMMIT() asm volatile("cp.async.commit_group;" ::: "memory")
#define CP_WAIT1()  asm volatile("cp.async.wait_group 1;" ::: "memory")
#define CP_WAIT0()  asm volatile("cp.async.wait_group 0;" ::: "memory")

#define LDSM_X4(r0, r1, r2, r3, addr)                                          \
  asm volatile("ldmatrix.sync.aligned.m8n8.x4.shared.b16 {%0,%1,%2,%3}, [%4];" \
               : "=r"(r0), "=r"(r1), "=r"(r2), "=r"(r3) : "r"(addr))

#define MMA_TF32(c0, c1, c2, c3, a0, a1, a2, a3, b0, b1)                       \
  asm volatile(                                                                \
      "mma.sync.aligned.m16n8k8.row.col.f32.tf32.tf32.f32 "                    \
      "{%0,%1,%2,%3}, {%4,%5,%6,%7}, {%8,%9}, {%0,%1,%2,%3};"                  \
      : "+f"(c0), "+f"(c1), "+f"(c2), "+f"(c3)                                 \
      : "r"(a0), "r"(a1), "r"(a2), "r"(a3), "r"(b0), "r"(b1))

__device__ __forceinline__ uint32_t sw128(uint32_t off) {
  return off ^ ((off >> 3) & 0x70);
}

__device__ __forceinline__ float rna_tf32(float x) {
  uint32_t t;
  asm("cvt.rna.tf32.f32 %0, %1;" : "=r"(t) : "f"(x));
  return __uint_as_float(t);
}

// ================= shared NT mma.sync tf32 mainloop ========================
// C[AROWS, *] += A[AROWS, 32*NCHUNK] * B[BROWS, 32*NCHUNK]^T (both K-major).
// Warp grid: wm = wid % WM_CNT (64 M-rows per warp), wn = wid / WM_CNT
// (32 N-cols per warp). AROWS = WM_CNT*64. SW128 smem rows of 128B.

template <int NTHREADS, int AROWS, int BROWS>
__device__ __forceinline__ void load_stage(uint32_t sbase, const float* Ag,
                                           int lda, const float* Bg, int ldb,
                                           int k0, int lr, int c4) {
  constexpr int RPP = NTHREADS / 8;          // rows per pass
  const uint32_t bbase = sbase + AROWS * 128u;
#pragma unroll
  for (int j = 0; j < AROWS / RPP; j++) {
    const int row = lr + j * RPP;
    CPA16(sbase + sw128((uint32_t)row * 128 + c4 * 16),
          Ag + (size_t)row * lda + k0 + c4 * 4);
  }
#pragma unroll
  for (int j = 0; j < BROWS / RPP; j++) {
    const int row = lr + j * RPP;
    CPA16(bbase + sw128((uint32_t)row * 128 + c4 * 16),
          Bg + (size_t)row * ldb + k0 + c4 * 4);
  }
}

template <int NTHREADS, int AROWS, int BROWS, int NCHUNK, int NSTAGES,
          int WM_CNT>
__device__ __forceinline__ void mma_mainloop(uint32_t smem_u, const float* Ag,
                                             int lda, const float* Bg, int ldb,
                                             float (&acc)[4][4][4]) {
  constexpr uint32_t STAGE = (AROWS + BROWS) * 128u;
  const int tid = threadIdx.x;
  const int lane = tid & 31, wid = tid >> 5;
  const int wm = wid % WM_CNT, wn = wid / WM_CNT;
  const int lr = tid >> 3, c4 = tid & 7;
  const int lb = lane >> 3, lrw = lane & 7;

  // validated fragment addressing (R10/R12/R13)
  const uint32_t a_row_base = wm * 64 + (lb & 1) * 8 + lrw;   // + mi*16
  const uint32_t a_kc_off = (lb >> 1) * 4;                    // + ks*8
  const uint32_t b_row_base = wn * 32 + (lb >> 1) * 8 + lrw;  // + np*16
  const uint32_t b_kc_off = (lb & 1) * 4;                     // + ks*8

  load_stage<NTHREADS, AROWS, BROWS>(smem_u, Ag, lda, Bg, ldb, 0, lr, c4);
  CP_COMMIT();
  if (NCHUNK > 1) {
    load_stage<NTHREADS, AROWS, BROWS>(smem_u + STAGE, Ag, lda, Bg, ldb, 32,
                                       lr, c4);
    CP_COMMIT();
  }

  for (int s = 0; s < NCHUNK; s++) {
    if (s + 1 < NCHUNK) CP_WAIT1(); else CP_WAIT0();
    __syncthreads();
    if (s + 2 < NCHUNK) {  // only real groups get committed
      load_stage<NTHREADS, AROWS, BROWS>(smem_u + ((s + 2) % NSTAGES) * STAGE,
                                         Ag, lda, Bg, ldb, (s + 2) * 32, lr,
                                         c4);
      CP_COMMIT();
    }

    const uint32_t ab = smem_u + (s % NSTAGES) * STAGE;
    const uint32_t bb = ab + AROWS * 128u;

#pragma unroll
    for (int ks = 0; ks < 4; ks++) {
      uint32_t af[4][4];
#pragma unroll
      for (int mi = 0; mi < 4; mi++) {
        const uint32_t addr = ab + sw128((a_row_base + mi * 16) * 128 +
                                         (ks * 8 + a_kc_off) * 4);
        LDSM_X4(af[mi][0], af[mi][1], af[mi][2], af[mi][3], addr);
      }
      uint32_t bf[4][2];
#pragma unroll
      for (int np = 0; np < 2; np++) {
        const uint32_t addr = bb + sw128((b_row_base + np * 16) * 128 +
                                         (ks * 8 + b_kc_off) * 4);
        uint32_t r0, r1, r2, r3;
        LDSM_X4(r0, r1, r2, r3, addr);
        bf[np * 2 + 0][0] = r0; bf[np * 2 + 0][1] = r1;
        bf[np * 2 + 1][0] = r2; bf[np * 2 + 1][1] = r3;
      }
#pragma unroll
      for (int mi = 0; mi < 4; mi++)
#pragma unroll
        for (int nj = 0; nj < 4; nj++)
          MMA_TF32(acc[mi][nj][0], acc[mi][nj][1], acc[mi][nj][2],
                   acc[mi][nj][3], af[mi][0], af[mi][1], af[mi][2], af[mi][3],
                   bf[nj][0], bf[nj][1]);
    }
  }
}

#define ACC_INIT(acc)                                                          \
  _Pragma("unroll") for (int i = 0; i < 4; i++)                                \
  _Pragma("unroll") for (int j = 0; j < 4; j++)                                \
  _Pragma("unroll") for (int r = 0; r < 4; r++) acc[i][j][r] = 0.f

// ===================== kernel: projections (NN via Wt) ======================
#define PROJ_SMEM (3 * 49152)
template <bool ROUND>
__global__ __launch_bounds__(512, 1) void proj_mma_kernel(
    const float* __restrict__ A, const float* __restrict__ Wt,
    const float* __restrict__ bias, float* __restrict__ C) {
  extern __shared__ char dsm[];
  const uint32_t smem_u = cvta_smem(dsm);
  const int bm = blockIdx.y * 256, bn = blockIdx.x * 128;

  float acc[4][4][4];
  ACC_INIT(acc);
  mma_mainloop<512, 256, 128, 32, 3, 4>(smem_u, A + (size_t)bm * Dc, Dc,
                                        Wt + (size_t)bn * Dc, Dc, acc);

  const int lane = threadIdx.x & 31, wid = threadIdx.x >> 5;
  const int wm = wid & 3, wn = wid >> 2;
  const int g = lane >> 2, n2 = (lane & 3) * 2;
#pragma unroll
  for (int mi = 0; mi < 4; mi++)
#pragma unroll
    for (int nj = 0; nj < 4; nj++) {
      const int row = bm + wm * 64 + mi * 16 + g;
      const int col = bn + wn * 32 + nj * 8 + n2;
      const float b0 = bias[col], b1 = bias[col + 1];
      float2 lo, hi;
      lo.x = acc[mi][nj][0] + b0; lo.y = acc[mi][nj][1] + b1;
      hi.x = acc[mi][nj][2] + b0; hi.y = acc[mi][nj][3] + b1;
      if (ROUND) {
        lo.x = rna_tf32(lo.x); lo.y = rna_tf32(lo.y);
        hi.x = rna_tf32(hi.x); hi.y = rna_tf32(hi.y);
      }
      *(float2*)(C + (size_t)row * Dc + col) = lo;
      *(float2*)(C + (size_t)(row + 8) * Dc + col) = hi;
    }
}

// ===================== kernel: masked scaled QK^T ===========================
#define QK_SMEM (2 * 49152)
__global__ __launch_bounds__(512, 1) void qk_mma_kernel(
    const int* __restrict__ mask) {
  extern __shared__ char dsm[];
  const uint32_t smem_u = cvta_smem(dsm);
  const int bh = blockIdx.z;
  const int b = bh >> 4, h = bh & 15;
  const int bm = blockIdx.y * 256, bn = blockIdx.x * 128;

  float acc[4][4][4];
  ACC_INIT(acc);
  mma_mainloop<512, 256, 128, 2, 2, 4>(
      smem_u, g_q + ((size_t)b * Sc + bm) * Dc + h * DKc, Dc,
      g_k + ((size_t)b * Sc + bn) * Dc + h * DKc, Dc, acc);

  const int lane = threadIdx.x & 31, wid = threadIdx.x >> 5;
  const int wm = wid & 3, wn = wid >> 2;
  const int g = lane >> 2, n2 = (lane & 3) * 2;
#pragma unroll
  for (int mi = 0; mi < 4; mi++)
#pragma unroll
    for (int nj = 0; nj < 4; nj++) {
      const int row = bm + wm * 64 + mi * 16 + g;
      const int col = bn + wn * 32 + nj * 8 + n2;
      const size_t m0 = ((size_t)b * Sc + row) * Sc + col;
      const size_t m1 = ((size_t)b * Sc + row + 8) * Sc + col;
      const int2 mk0 = *(const int2*)(mask + m0);
      const int2 mk1 = *(const int2*)(mask + m1);
      float2 lo, hi;
      lo.x = mk0.x ? rna_tf32(acc[mi][nj][0] * 0.125f) : 0.f;
      lo.y = mk0.y ? rna_tf32(acc[mi][nj][1] * 0.125f) : 0.f;
      hi.x = mk1.x ? rna_tf32(acc[mi][nj][2] * 0.125f) : 0.f;
      hi.y = mk1.y ? rna_tf32(acc[mi][nj][3] * 0.125f) : 0.f;
      *(float2*)(g_s1 + ((size_t)bh * Sc + row) * Sc + col) = lo;
      *(float2*)(g_s1 + ((size_t)bh * Sc + row + 8) * Sc + col) = hi;
    }
}

// ===================== kernel: propagation GEMM =============================
// S2[m,l] = sum_k S1[m,k] * P[l,k]   (M=65536, N=2048, K=2048)
// 256 threads, tile 128x128, 3x32KB stages -> occupancy 2.
#define PROP_SMEM (3 * 32768)
__global__ __launch_bounds__(256, 2) void prop_mma_kernel() {
  extern __shared__ char dsm[];
  const uint32_t smem_u = cvta_smem(dsm);
  const int bm = blockIdx.y * 128, bn = blockIdx.x * 128;

  float acc[4][4][4];
  ACC_INIT(acc);
  mma_mainloop<256, 128, 128, 64, 3, 2>(smem_u, g_s1 + (size_t)bm * Sc, Sc,
                                        g_p + (size_t)bn * Sc, Sc, acc);

  const int lane = threadIdx.x & 31, wid = threadIdx.x >> 5;
  const int wm = wid & 1, wn = wid >> 1;
  const int g = lane >> 2, n2 = (lane & 3) * 2;
#pragma unroll
  for (int mi = 0; mi < 4; mi++)
#pragma unroll
    for (int nj = 0; nj < 4; nj++) {
      const int row = bm + wm * 64 + mi * 16 + g;
      const int col = bn + wn * 32 + nj * 8 + n2;
      float2 lo, hi;
      lo.x = acc[mi][nj][0]; lo.y = acc[mi][nj][1];
      hi.x = acc[mi][nj][2]; hi.y = acc[mi][nj][3];
      *(float2*)(g_s2 + (size_t)row * Sc + col) = lo;
      *(float2*)(g_s2 + (size_t)(row + 8) * Sc + col) = hi;
    }
}

// ===================== kernel: P @ V (per head) =============================
#define AV_SMEM (3 * 40960)
__global__ __launch_bounds__(256, 1) void av_mma_kernel() {
  extern __shared__ char dsm[];
  const uint32_t smem_u = cvta_smem(dsm);
  const int bh = blockIdx.z;
  const int b = bh >> 4, h = bh & 15;
  const int bm = blockIdx.y * 256;

  float acc[4][4][4];
  ACC_INIT(acc);
  mma_mainloop<256, 256, 64, 64, 3, 4>(smem_u,
                                       g_s2 + ((size_t)bh * Sc + bm) * Sc, Sc,
                                       g_vt + (size_t)bh * DKc * Sc, Sc, acc);

  const int lane = threadIdx.x & 31, wid = threadIdx.x >> 5;
  const int wm = wid & 3, wn = wid >> 2;   // wn in {0,1}
  const int g = lane >> 2, n2 = (lane & 3) * 2;
#pragma unroll
  for (int mi = 0; mi < 4; mi++)
#pragma unroll
    for (int nj = 0; nj < 4; nj++) {
      const int row = bm + wm * 64 + mi * 16 + g;
      const int col = wn * 32 + nj * 8 + n2;   // 0..63
      float2 lo, hi;
      lo.x = rna_tf32(acc[mi][nj][0]); lo.y = rna_tf32(acc[mi][nj][1]);
      hi.x = rna_tf32(acc[mi][nj][2]); hi.y = rna_tf32(acc[mi][nj][3]);
      *(float2*)(g_ctx + ((size_t)b * Sc + row) * Dc + h * DKc + col) = lo;
      *(float2*)(g_ctx + ((size_t)b * Sc + row + 8) * Dc + h * DKc + col) = hi;
    }
}

// ====================== transposes and rounding =============================
__global__ __launch_bounds__(1024) void transpose_w_kernel(
    const float* __restrict__ W, float* __restrict__ Wt) {
  __shared__ float t[32][33];
  const int tx = threadIdx.x, ty = threadIdx.y;
  const int n0 = blockIdx.x * 32, k0 = blockIdx.y * 32;
  t[ty][tx] = W[(size_t)(k0 + ty) * Dc + n0 + tx];
  __syncthreads();
  Wt[(size_t)(n0 + ty) * Dc + k0 + tx] = rna_tf32(t[tx][ty]);
}

__global__ __launch_bounds__(1024) void transpose_v_kernel() {
  __shared__ float t[32][33];
  const int tx = threadIdx.x, ty = threadIdx.y;
  const int bh = blockIdx.z;
  const int b = bh >> 4, h = bh & 15;
  const int l0 = blockIdx.x * 32, d0 = blockIdx.y * 32;
  t[ty][tx] = g_v[((size_t)b * Sc + l0 + ty) * Dc + h * DKc + d0 + tx];
  __syncthreads();
  g_vt[(size_t)bh * DKc * Sc + (size_t)(d0 + ty) * Sc + l0 + tx] =
      rna_tf32(t[tx][ty]);
}

__global__ __launch_bounds__(256) void tf32_round_kernel(
    const float4* __restrict__ src, float4* __restrict__ dst) {
  const int i = blockIdx.x * 256 + threadIdx.x;
  float4 v = src[i];
  float4 o;
  o.x = rna_tf32(v.x); o.y = rna_tf32(v.y);
  o.z = rna_tf32(v.z); o.w = rna_tf32(v.w);
  dst[i] = o;
}

// ========== masked softmax, single pass, register-cached row ================
__global__ __launch_bounds__(256) void softmax_kernel(const int* __restrict__ mask) {
  const int row = blockIdx.x;           // (b*H+h)*S + q
  const int b = row >> 15;
  const int q = row & (Sc - 1);
  float* p = g_s2 + (size_t)row * Sc;
  const int* mrow = mask + ((size_t)b * Sc + q) * Sc;
  const int tid = threadIdx.x;
  const int base = tid * 8;
  __shared__ float red[8];

  float e[8];
  int mm[8];
  {
    float4 v0 = *(const float4*)(p + base);
    float4 v1 = *(const float4*)(p + base + 4);
    int4 k0 = *(const int4*)(mrow + base);
    int4 k1 = *(const int4*)(mrow + base + 4);
    e[0] = v0.x; e[1] = v0.y; e[2] = v0.z; e[3] = v0.w;
    e[4] = v1.x; e[5] = v1.y; e[6] = v1.z; e[7] = v1.w;
    mm[0] = k0.x; mm[1] = k0.y; mm[2] = k0.z; mm[3] = k0.w;
    mm[4] = k1.x; mm[5] = k1.y; mm[6] = k1.z; mm[7] = k1.w;
  }

  // block max over masked entries
  float mx = -3.402823466e38f;
#pragma unroll
  for (int j = 0; j < 8; j++)
    if (mm[j]) mx = fmaxf(mx, e[j]);
#pragma unroll
  for (int o = 16; o > 0; o >>= 1)
    mx = fmaxf(mx, __shfl_xor_sync(0xffffffffu, mx, o));
  if ((tid & 31) == 0) red[tid >> 5] = mx;
  __syncthreads();
  mx = red[0];
#pragma unroll
  for (int w = 1; w < 8; w++) mx = fmaxf(mx, red[w]);
  __syncthreads();

  // exp + block sum
  float sum = 0.f;
#pragma unroll
  for (int j = 0; j < 8; j++) {
    e[j] = mm[j] ? expf(e[j] - mx) : 0.f;
    sum += e[j];
  }
#pragma unroll
  for (int o = 16; o > 0; o >>= 1)
    sum += __shfl_xor_sync(0xffffffffu, sum, o);
  if ((tid & 31) == 0) red[tid >> 5] = sum;
  __syncthreads();
  sum = 0.f;
#pragma unroll
  for (int w = 0; w < 8; w++) sum += red[w];

  const float inv = sum > 0.f ? 1.f / sum : 0.f;  // nan_to_num
  float4 o0, o1;
  o0.x = rna_tf32(e[0] * inv); o0.y = rna_tf32(e[1] * inv);
  o0.z = rna_tf32(e[2] * inv); o0.w = rna_tf32(e[3] * inv);
  o1.x = rna_tf32(e[4] * inv); o1.y = rna_tf32(e[5] * inv);
  o1.z = rna_tf32(e[6] * inv); o1.w = rna_tf32(e[7] * inv);
  *(float4*)(p + base) = o0;
  *(float4*)(p + base + 4) = o1;
}

// ---------------------------------------------------------------------------
extern "C" void kernel_launch(void* const* d_in, const int* in_sizes, int n_in,
                              void* d_out, int out_size) {
  const float* in_q = (const float*)d_in[0];
  const float* in_k = (const float*)d_in[1];
  const float* in_v = (const float*)d_in[2];
  const int*   mask = (const int*)d_in[3];
  const float* prop = (const float*)d_in[4];
  const float* Wq = (const float*)d_in[5];
  const float* bq = (const float*)d_in[6];
  const float* Wk = (const float*)d_in[7];
  const float* bk = (const float*)d_in[8];
  const float* Wv = (const float*)d_in[9];
  const float* bv = (const float*)d_in[10];
  const float* Wo = (const float*)d_in[11];
  const float* bo = (const float*)d_in[12];
  float* out = (float*)d_out;

  float *qp, *kp, *vp, *ctxp, *pp, *wtp, *s1p;
  cudaGetSymbolAddress((void**)&qp, g_q);
  cudaGetSymbolAddress((void**)&kp, g_k);
  cudaGetSymbolAddress((void**)&vp, g_v);
  cudaGetSymbolAddress((void**)&ctxp, g_ctx);
  cudaGetSymbolAddress((void**)&pp, g_p);
  cudaGetSymbolAddress((void**)&wtp, g_wt);
  cudaGetSymbolAddress((void**)&s1p, g_s1);

  cudaFuncSetAttribute(proj_mma_kernel<true>,
                       cudaFuncAttributeMaxDynamicSharedMemorySize, PROJ_SMEM);
  cudaFuncSetAttribute(proj_mma_kernel<false>,
                       cudaFuncAttributeMaxDynamicSharedMemorySize, PROJ_SMEM);
  cudaFuncSetAttribute(qk_mma_kernel,
                       cudaFuncAttributeMaxDynamicSharedMemorySize, QK_SMEM);
  cudaFuncSetAttribute(prop_mma_kernel,
                       cudaFuncAttributeMaxDynamicSharedMemorySize, PROP_SMEM);
  cudaFuncSetAttribute(av_mma_kernel,
                       cudaFuncAttributeMaxDynamicSharedMemorySize, AV_SMEM);

  const int XN = BSc * Dc;               // 4,194,304 elems per input
  float* xq = s1p;                       // rounded-input scratch lives in the
  float* xk = s1p + XN;                  // head of g_s1 (dead until qk writes)
  float* xv = s1p + 2 * XN;
  float* wt0 = wtp, *wt1 = wtp + Dc * Dc, *wt2 = wtp + 2 * Dc * Dc,
        *wt3 = wtp + 3 * Dc * Dc;

  // 0) round inputs to tf32; transpose+round weights
  tf32_round_kernel<<<XN / 1024, 256>>>((const float4*)in_q, (float4*)xq);
  tf32_round_kernel<<<XN / 1024, 256>>>((const float4*)in_k, (float4*)xk);
  tf32_round_kernel<<<XN / 1024, 256>>>((const float4*)in_v, (float4*)xv);
  dim3 tb(32, 32);
  transpose_w_kernel<<<dim3(32, 32), tb>>>(Wq, wt0);
  transpose_w_kernel<<<dim3(32, 32), tb>>>(Wk, wt1);
  transpose_w_kernel<<<dim3(32, 32), tb>>>(Wv, wt2);
  transpose_w_kernel<<<dim3(32, 32), tb>>>(Wo, wt3);

  // 1) projections (Q/K rounded for qk mma; V rounded in transpose_v)
  dim3 gproj(Dc / 128, BSc / 256);       // (8, 16)
  proj_mma_kernel<true><<<gproj, 512, PROJ_SMEM>>>(xq, wt0, bq, qp);
  proj_mma_kernel<true><<<gproj, 512, PROJ_SMEM>>>(xk, wt1, bk, kp);
  proj_mma_kernel<false><<<gproj, 512, PROJ_SMEM>>>(xv, wt2, bv, vp);
  transpose_v_kernel<<<dim3(Sc / 32, DKc / 32, BHc), tb>>>();

  // 2) masked scaled QK^T
  qk_mma_kernel<<<dim3(Sc / 128, Sc / 256, BHc), 512, QK_SMEM>>>(mask);

  // 3) attention propagation (dominant; occupancy-2 config)
  tf32_round_kernel<<<(Sc * Sc) / 1024, 256>>>((const float4*)prop, (float4*)pp);
  prop_mma_kernel<<<dim3(Sc / 128, (BHc * Sc) / 128), 256, PROP_SMEM>>>();

  // 4) masked softmax + nan_to_num (rounds P for av mma)
  softmax_kernel<<<BHc * Sc, 256>>>(mask);

  // 5) P @ V
  av_mma_kernel<<<dim3(1, Sc / 256, BHc), 256, AV_SMEM>>>();

  // 6) output projection
  proj_mma_kernel<false><<<gproj, 512, PROJ_SMEM>>>(ctxp, wt3, bo, out);
}